// round 16
// baseline (speedup 1.0000x reference)
#include <cuda_runtime.h>
#include <cuda_bf16.h>
#include <cuda_fp16.h>
#include <cstdint>

#define NTOK  8192
#define INDIM 1024
#define CDIM  512

using bf16 = __nv_bfloat16;

// bf16 hi/lo packed tile: 128 rows x 32 cols, pitch 80 B; hi then lo. 20480 B.
#define TILE_B  20480
#define TILE_HI 10240
// fp16 single-plane tile: 128 rows x 32 cols, pitch 80 B. 10240 B.
#define PTILE   10240

// ---------------------------------------------------------------------------
__device__ __align__(1024) char g_Sp[(size_t)2048 * TILE_B];    // S: [rb 64][kc 32] bf16 hi/lo
__device__ __align__(1024) char g_Wp[3][(size_t)128 * TILE_B];  // W: [rb 4][kc 32] bf16 hi/lo
__device__ __align__(1024) char g_Qp[(size_t)1024 * TILE_B];    // Q: [rb 64][kc 16] bf16 hi/lo
__device__ __align__(1024) char g_Kp[(size_t)1024 * TILE_B];    // K: [rb 64][kc 16] bf16 hi/lo
__device__ __align__(1024) char g_Vtp[(size_t)1024 * PTILE];    // V^T: [rb 4][kc 256] fp16
__device__ __align__(1024) char g_Pp[(size_t)16384 * PTILE];    // P: [rb 64][kc 256] fp16
__device__ float g_rowsum[NTOK];

// ---------------------------------------------------------------------------
__device__ __forceinline__ uint32_t su32(const void* p) {
    uint32_t a;
    asm("{ .reg .u64 t; cvta.to.shared.u64 t, %1; cvt.u32.u64 %0, t; }" : "=r"(a) : "l"(p));
    return a;
}
__device__ __forceinline__ void mbar_init(uint32_t m, uint32_t c) {
    asm volatile("mbarrier.init.shared.b64 [%0], %1;" :: "r"(m), "r"(c) : "memory");
}
__device__ __forceinline__ void mbar_expect(uint32_t m, uint32_t bytes) {
    asm volatile("mbarrier.arrive.expect_tx.shared.b64 _, [%0], %1;" :: "r"(m), "r"(bytes) : "memory");
}
__device__ __forceinline__ void mbar_wait(uint32_t m, uint32_t parity) {
    asm volatile(
        "{\n\t.reg .pred P1;\n\t"
        "WL_%=:\n\t"
        "mbarrier.try_wait.parity.acquire.cta.shared::cta.b64 P1, [%0], %1, 0x989680;\n\t"
        "@P1 bra.uni WD_%=;\n\t"
        "bra.uni WL_%=;\n\t"
        "WD_%=:\n\t}"
        :: "r"(m), "r"(parity) : "memory");
}
__device__ __forceinline__ void bulk_g2s(uint32_t sdst, const void* gsrc, uint32_t bytes, uint32_t mbar) {
    asm volatile(
        "cp.async.bulk.shared::cluster.global.mbarrier::complete_tx::bytes [%0], [%1], %2, [%3];"
        :: "r"(sdst), "l"(__cvta_generic_to_global(gsrc)), "r"(bytes), "r"(mbar) : "memory");
}
__device__ __forceinline__ void ldm4(uint32_t& r0, uint32_t& r1, uint32_t& r2, uint32_t& r3, uint32_t a) {
    asm volatile("ldmatrix.sync.aligned.m8n8.x4.shared.b16 {%0,%1,%2,%3}, [%4];"
                 : "=r"(r0), "=r"(r1), "=r"(r2), "=r"(r3) : "r"(a));
}
__device__ __forceinline__ void mma16816(float* c, const uint32_t* a, const uint32_t* b) {
    asm volatile(
        "mma.sync.aligned.m16n8k16.row.col.f32.bf16.bf16.f32 "
        "{%0,%1,%2,%3}, {%4,%5,%6,%7}, {%8,%9}, {%0,%1,%2,%3};"
        : "+f"(c[0]), "+f"(c[1]), "+f"(c[2]), "+f"(c[3])
        : "r"(a[0]), "r"(a[1]), "r"(a[2]), "r"(a[3]), "r"(b[0]), "r"(b[1]));
}
__device__ __forceinline__ void mmaf16(float* c, const uint32_t* a, const uint32_t* b) {
    asm volatile(
        "mma.sync.aligned.m16n8k16.row.col.f32.f16.f16.f32 "
        "{%0,%1,%2,%3}, {%4,%5,%6,%7}, {%8,%9}, {%0,%1,%2,%3};"
        : "+f"(c[0]), "+f"(c[1]), "+f"(c[2]), "+f"(c[3])
        : "r"(a[0]), "r"(a[1]), "r"(a[2]), "r"(a[3]), "r"(b[0]), "r"(b[1]));
}
__device__ __forceinline__ void split2(float v, bf16& h, bf16& l) {
    h = __float2bfloat16(v);
    l = __float2bfloat16(v - __bfloat162float(h));
}
__device__ __forceinline__ uint32_t packbf(bf16 a, bf16 b) {
    return ((uint32_t)__bfloat16_as_ushort(b) << 16) | __bfloat16_as_ushort(a);
}

// ---------------------------------------------------------------------------
// bf16 GEMM SMEM: stage = [A_HI][A_LO][B_HI][B_LO] = 40960 B; x2 stages.
#define A_HI   0
#define A_LO   10240
#define B_HI   20480
#define B_LO   30720
#define STAGE  40960
#define SM_RSUM 81920
#define SM_MBAR 82432           // 4 mbarriers x 8 B
#define SM_TOTAL 82464
// av (fp16) SMEM: stage = [A 10240][B 10240] = 20480 B; x4 stages = 81920 B.
#define AVSTAGE 20480
#define AV_NST  4

// bf16 x3-combo chunk into acc[4][4][4].
__device__ __forceinline__ void compute_stage(uint32_t sb, int wm, int wn, int lane,
                                              float acc[4][4][4])
{
    const uint32_t a_off = (lane & 15) * 80 + (lane >> 4) * 16;
    const uint32_t b_off = ((lane & 7) + ((lane >> 4) & 1) * 8) * 80 + ((lane >> 3) & 1) * 16;
#pragma unroll
    for (int kk = 0; kk < 2; kk++) {
        uint32_t bh[8], bl[8], a[16];
#pragma unroll
        for (int jj = 0; jj < 2; jj++) {
            uint32_t ad = sb + B_HI + (wn * 32 + jj * 16) * 80 + kk * 32 + b_off;
            ldm4(bh[jj * 4], bh[jj * 4 + 1], bh[jj * 4 + 2], bh[jj * 4 + 3], ad);
            ldm4(bl[jj * 4], bl[jj * 4 + 1], bl[jj * 4 + 2], bl[jj * 4 + 3], ad + (B_LO - B_HI));
        }
#pragma unroll
        for (int i = 0; i < 4; i++) {
            uint32_t ad = sb + A_HI + (wm * 64 + i * 16) * 80 + kk * 32 + a_off;
            ldm4(a[i * 4], a[i * 4 + 1], a[i * 4 + 2], a[i * 4 + 3], ad);
        }
#pragma unroll
        for (int i = 0; i < 4; i++)
#pragma unroll
            for (int j = 0; j < 4; j++) {
                mma16816(acc[i][j], &a[i * 4], &bh[j * 2]);
                mma16816(acc[i][j], &a[i * 4], &bl[j * 2]);
            }
#pragma unroll
        for (int i = 0; i < 4; i++) {
            uint32_t ad = sb + A_LO + (wm * 64 + i * 16) * 80 + kk * 32 + a_off;
            ldm4(a[i * 4], a[i * 4 + 1], a[i * 4 + 2], a[i * 4 + 3], ad);
        }
#pragma unroll
        for (int i = 0; i < 4; i++)
#pragma unroll
            for (int j = 0; j < 4; j++)
                mma16816(acc[i][j], &a[i * 4], &bh[j * 2]);
    }
}

// fp16 1-combo chunk (av) into acc[4][4][4].
__device__ __forceinline__ void compute_av(uint32_t sb, int wm, int wn, int lane,
                                           float acc[4][4][4])
{
    const uint32_t a_off = (lane & 15) * 80 + (lane >> 4) * 16;
    const uint32_t b_off = ((lane & 7) + ((lane >> 4) & 1) * 8) * 80 + ((lane >> 3) & 1) * 16;
#pragma unroll
    for (int kk = 0; kk < 2; kk++) {
        uint32_t bh[8], a[16];
#pragma unroll
        for (int jj = 0; jj < 2; jj++) {
            uint32_t ad = sb + PTILE + (wn * 32 + jj * 16) * 80 + kk * 32 + b_off;
            ldm4(bh[jj * 4], bh[jj * 4 + 1], bh[jj * 4 + 2], bh[jj * 4 + 3], ad);
        }
#pragma unroll
        for (int i = 0; i < 4; i++) {
            uint32_t ad = sb + (wm * 64 + i * 16) * 80 + kk * 32 + a_off;
            ldm4(a[i * 4], a[i * 4 + 1], a[i * 4 + 2], a[i * 4 + 3], ad);
        }
#pragma unroll
        for (int i = 0; i < 4; i++)
#pragma unroll
            for (int j = 0; j < 4; j++)
                mmaf16(acc[i][j], &a[i * 4], &bh[j * 2]);
    }
}

#define ISSUE_CHUNK(kc)                                                                      \
    do {                                                                                     \
        uint32_t s_ = sb + ((kc) & 1) * STAGE;                                               \
        uint32_t m_ = ((kc) & 1) ? mb1 : mb0;                                                \
        mbar_expect(m_, 2 * TILE_B);                                                         \
        bulk_g2s(s_,        Abase + (size_t)(at0 + (kc)) * TILE_B, TILE_B, m_);              \
        bulk_g2s(s_ + B_HI, Bbase + (size_t)(bt0 + (kc)) * TILE_B, TILE_B, m_);              \
    } while (0)

#define PACKED_MAINLOOP(AbaseE, at0E, BbaseE, bt0E, NCH)                                     \
    const char* Abase = (AbaseE); const char* Bbase = (BbaseE);                              \
    const int at0 = (at0E), bt0 = (bt0E);                                                    \
    if (tid == 0) { mbar_init(mb0, 1); mbar_init(mb1, 1); }                                  \
    __syncthreads();                                                                         \
    if (tid == 0) { ISSUE_CHUNK(0); ISSUE_CHUNK(1); }                                        \
    for (int kc = 0; kc < (NCH); kc++) {                                                     \
        mbar_wait((kc & 1) ? mb1 : mb0, (uint32_t)((kc >> 1) & 1));                          \
        compute_stage(sb + (kc & 1) * STAGE, wm, wn, lane, acc);                             \
        __syncthreads();                                                                     \
        if (tid == 0 && kc + 2 < (NCH)) ISSUE_CHUNK(kc + 2);                                 \
    }

#define AV_ISSUE(kc)                                                                         \
    do {                                                                                     \
        int st_ = (kc) & 3;                                                                  \
        uint32_t s_ = sb + st_ * AVSTAGE;                                                    \
        uint32_t m_ = sb + SM_MBAR + st_ * 8;                                                \
        mbar_expect(m_, 2 * PTILE);                                                          \
        bulk_g2s(s_,         g_Pp  + (size_t)(at0 + (kc)) * PTILE, PTILE, m_);               \
        bulk_g2s(s_ + PTILE, g_Vtp + (size_t)(bt0 + (kc)) * PTILE, PTILE, m_);               \
    } while (0)

#define GEMM_PROLOG                                                   \
    extern __shared__ char smem[];                                    \
    const uint32_t sb = su32(smem);                                   \
    const uint32_t mb0 = sb + SM_MBAR, mb1 = sb + SM_MBAR + 8;        \
    const int tid = threadIdx.x;                                      \
    const int lane = tid & 31, warp = tid >> 5;                       \
    const int wm = warp >> 2, wn = warp & 3;                          \
    float acc[4][4][4];                                               \
    _Pragma("unroll") for (int i = 0; i < 4; i++)                     \
    _Pragma("unroll") for (int j = 0; j < 4; j++)                     \
    _Pragma("unroll") for (int k = 0; k < 4; k++) acc[i][j][k] = 0.0f;

// ---------------------------------------------------------------------------
// Fused split: blocks [0, 4096) -> S (also zeroes rowsum); [4096, 4864) -> W.
__global__ __launch_bounds__(256) void split_all_kernel(
    const float* __restrict__ u, const float* __restrict__ z,
    const float* __restrict__ Wk, const float* __restrict__ Wv, const float* __restrict__ Wq)
{
    if (blockIdx.x < 4096) {
        int idx = blockIdx.x * 256 + threadIdx.x;
        if (idx < NTOK) g_rowsum[idx] = 0.0f;
        int row = idx >> 7;
        int c0 = (idx & 127) * 8;
        const float* src = (c0 < 512) ? (u + (size_t)row * 512 + c0)
                                      : (z + (size_t)row * 512 + c0 - 512);
        float4 a = *(const float4*)src;
        float4 b = *(const float4*)(src + 4);
        float x[8] = {a.x, a.y, a.z, a.w, b.x, b.y, b.z, b.w};
        uint32_t hw[4], lw[4];
#pragma unroll
        for (int i = 0; i < 4; i++) {
            bf16 h0, l0, h1, l1;
            split2(x[2 * i], h0, l0); split2(x[2 * i + 1], h1, l1);
            hw[i] = packbf(h0, h1); lw[i] = packbf(l0, l1);
        }
        size_t t = (size_t)(row >> 7) * 32 + (c0 >> 5);
        size_t off = t * TILE_B + (size_t)(row & 127) * 80 + (c0 & 31) * 2;
        *(uint4*)(g_Sp + off)           = make_uint4(hw[0], hw[1], hw[2], hw[3]);
        *(uint4*)(g_Sp + off + TILE_HI) = make_uint4(lw[0], lw[1], lw[2], lw[3]);
    } else {
        int wb = blockIdx.x - 4096;            // 0..767
        int sel = wb >> 8;                     // 256 blocks per W
        const float* W = (sel == 0) ? Wk : (sel == 1) ? Wv : Wq;
        int idx = (wb & 255) * 256 + threadIdx.x;
        int row = idx >> 7;
        int c0 = (idx & 127) * 8;
        const float* src = W + (size_t)row * INDIM + c0;
        float4 a = *(const float4*)src;
        float4 b = *(const float4*)(src + 4);
        float x[8] = {a.x, a.y, a.z, a.w, b.x, b.y, b.z, b.w};
        uint32_t hw[4], lw[4];
#pragma unroll
        for (int i = 0; i < 4; i++) {
            bf16 h0, l0, h1, l1;
            split2(x[2 * i], h0, l0); split2(x[2 * i + 1], h1, l1);
            hw[i] = packbf(h0, h1); lw[i] = packbf(l0, l1);
        }
        size_t t = (size_t)(row >> 7) * 32 + (c0 >> 5);
        size_t off = t * TILE_B + (size_t)(row & 127) * 80 + (c0 & 31) * 2;
        *(uint4*)(g_Wp[sel] + off)           = make_uint4(hw[0], hw[1], hw[2], hw[3]);
        *(uint4*)(g_Wp[sel] + off + TILE_HI) = make_uint4(lw[0], lw[1], lw[2], lw[3]);
    }
}

// ---------------------------------------------------------------------------
// Projection (all three in one launch): tile 128x128, K=1024.
// blockIdx.z: 0->K (bf16 hi/lo), 1->V (transposed fp16), 2->Q (bf16 hi/lo)
__global__ __launch_bounds__(256, 2) void proj_k(
    const float* __restrict__ bk, const float* __restrict__ bv, const float* __restrict__ bq)
{
    GEMM_PROLOG;
    const int sel = blockIdx.z;
    const float* bias = (sel == 0) ? bk : (sel == 1) ? bv : bq;
    const int row0 = blockIdx.y * 128, col0 = blockIdx.x * 128;
    {
        PACKED_MAINLOOP(g_Sp, (row0 >> 7) * 32, g_Wp[sel], (col0 >> 7) * 32, INDIM / 32);
    }

    if (sel != 1) {
        char* outp = (sel == 2) ? g_Qp : g_Kp;
#pragma unroll
        for (int i = 0; i < 4; i++)
#pragma unroll
            for (int hb = 0; hb < 2; hb++) {
                int grow = row0 + wm * 64 + i * 16 + (lane >> 2) + hb * 8;
                char* base = outp
                    + ((size_t)(grow >> 7) * 16 + (col0 >> 5) + wn) * TILE_B
                    + (size_t)(grow & 127) * 80 + (lane & 3) * 4;
#pragma unroll
                for (int j = 0; j < 4; j++) {
                    int gcol = col0 + wn * 32 + j * 8 + (lane & 3) * 2;
                    float v0 = acc[i][j][hb * 2]     + __ldg(bias + gcol);
                    float v1 = acc[i][j][hb * 2 + 1] + __ldg(bias + gcol + 1);
                    bf16 h0, l0, h1, l1;
                    split2(v0, h0, l0); split2(v1, h1, l1);
                    *(uint32_t*)(base + j * 16)           = packbf(h0, h1);
                    *(uint32_t*)(base + j * 16 + TILE_HI) = packbf(l0, l1);
                }
            }
    } else {
        // V: fp16, transpose via smem (single plane, pitch 272 B; [c 128][tok 128]).
#pragma unroll
        for (int i = 0; i < 4; i++)
#pragma unroll
            for (int hb = 0; hb < 2; hb++) {
                int tok = wm * 64 + i * 16 + (lane >> 2) + hb * 8;
#pragma unroll
                for (int j = 0; j < 4; j++) {
                    int cl = wn * 32 + j * 8 + (lane & 3) * 2;
                    float v0 = acc[i][j][hb * 2]     + __ldg(bias + col0 + cl);
                    float v1 = acc[i][j][hb * 2 + 1] + __ldg(bias + col0 + cl + 1);
                    *(__half*)(smem + cl * 272 + tok * 2)       = __float2half(v0);
                    *(__half*)(smem + (cl + 1) * 272 + tok * 2) = __float2half(v1);
                }
            }
        __syncthreads();
        for (int q = tid; q < 2048; q += 256) {
            int c = q >> 4, t8 = (q & 15) * 8;
            uint4 vh = *(uint4*)(smem + c * 272 + t8 * 2);
            size_t t = (size_t)(col0 >> 7) * 256 + ((row0 + t8) >> 5);
            size_t off = t * PTILE + (size_t)c * 80 + (t8 & 31) * 2;
            *(uint4*)(g_Vtp + off) = vh;
        }
    }
}

// ---------------------------------------------------------------------------
// Scores: P = exp(QK^T/sqrt(512)) unnormalized, diag=0, stored fp16; rowsum.
// Off-diagonal CTAs (row0 != col0) take a compare-free epilogue.
__global__ __launch_bounds__(256, 2) void scores_k()
{
    GEMM_PROLOG;
    const int row0 = blockIdx.y * 128, col0 = blockIdx.x * 128;
    float* s_rsum = (float*)(smem + SM_RSUM);
    if (tid < 128) s_rsum[tid] = 0.0f;
    {
        PACKED_MAINLOOP(g_Qp, (row0 >> 7) * 16, g_Kp, (col0 >> 7) * 16, CDIM / 32);
    }

    // exp(x/sqrt(512)) = exp2(x * log2(e)/sqrt(512))
    const float scale2 = 0.06375871712f;
    const bool offdiag = (row0 != col0);
#pragma unroll
    for (int i = 0; i < 4; i++)
#pragma unroll
        for (int hb = 0; hb < 2; hb++) {
            int rloc = wm * 64 + i * 16 + (lane >> 2) + hb * 8;
            int grow = row0 + rloc;
            char* base = g_Pp
                + ((size_t)(grow >> 7) * 256 + (col0 >> 5) + wn) * PTILE
                + (size_t)(grow & 127) * 80 + (lane & 3) * 4;
            float part = 0.0f;
            if (offdiag) {
#pragma unroll
                for (int j = 0; j < 4; j++) {
                    float p0 = exp2f(acc[i][j][hb * 2]     * scale2);
                    float p1 = exp2f(acc[i][j][hb * 2 + 1] * scale2);
                    part += p0 + p1;
                    __half2 ph = __floats2half2_rn(p0, p1);
                    __stcs((unsigned int*)(base + j * 16), *(unsigned int*)&ph);
                }
            } else {
#pragma unroll
                for (int j = 0; j < 4; j++) {
                    int gcol = col0 + wn * 32 + j * 8 + (lane & 3) * 2;
                    float p0 = (grow == gcol)     ? 0.0f : exp2f(acc[i][j][hb * 2]     * scale2);
                    float p1 = (grow == gcol + 1) ? 0.0f : exp2f(acc[i][j][hb * 2 + 1] * scale2);
                    part += p0 + p1;
                    __half2 ph = __floats2half2_rn(p0, p1);
                    __stcs((unsigned int*)(base + j * 16), *(unsigned int*)&ph);
                }
            }
            part += __shfl_xor_sync(0xFFFFFFFF, part, 1);
            part += __shfl_xor_sync(0xFFFFFFFF, part, 2);
            if ((lane & 3) == 0) atomicAdd(&s_rsum[rloc], part);
        }
    __syncthreads();
    if (tid < 128) atomicAdd(&g_rowsum[row0 + tid], s_rsum[tid]);
}

// ---------------------------------------------------------------------------
// AV: m_bar = (P @ V) / rowsum, fp16 x fp16, 1 combo, tile 128x128, K=8192.
// 4-stage bulk pipeline (latency cover for the short fp16 chunks).
// FUSED: each CTA converts its quarter of the P row-block (kc>>6 == blockIdx.x)
// from smem to normalized fp32 attn.
__global__ __launch_bounds__(256, 2) void av_k(float* __restrict__ m_out,
                                               float* __restrict__ attn)
{
    GEMM_PROLOG;
    const int row0 = blockIdx.y * 128, col0 = blockIdx.x * 128;
    const int cvt_sel = blockIdx.x;
    const int crow = tid >> 1;               // conversion row 0..127
    const int cseg = (tid & 1) * 16;         // col segment 0 or 16
    const float cinv = 1.0f / g_rowsum[row0 + crow];

    const int at0 = (row0 >> 7) * 256, bt0 = (col0 >> 7) * 256;
    if (tid == 0) {
#pragma unroll
        for (int s = 0; s < AV_NST; s++) mbar_init(sb + SM_MBAR + s * 8, 1);
    }
    __syncthreads();
    if (tid == 0) { AV_ISSUE(0); AV_ISSUE(1); AV_ISSUE(2); AV_ISSUE(3); }
    for (int kc = 0; kc < NTOK / 32; kc++) {
        int st = kc & 3;
        mbar_wait(sb + SM_MBAR + st * 8, (uint32_t)((kc >> 2) & 1));
        compute_av(sb + st * AVSTAGE, wm, wn, lane, acc);
        if ((kc >> 6) == cvt_sel) {
            uint32_t soff = st * AVSTAGE + (uint32_t)crow * 80 + cseg * 2;
            uint4 h0 = *(uint4*)(smem + soff);
            uint4 h1 = *(uint4*)(smem + soff + 16);
            uint32_t hw[8] = {h0.x, h0.y, h0.z, h0.w, h1.x, h1.y, h1.z, h1.w};
            float o[16];
#pragma unroll
            for (int k = 0; k < 8; k++) {
                float2 f = __half22float2(*reinterpret_cast<__half2*>(&hw[k]));
                o[2 * k]     = f.x * cinv;
                o[2 * k + 1] = f.y * cinv;
            }
            float* dst = attn + (size_t)(row0 + crow) * NTOK + kc * 32 + cseg;
            __stcs((float4*)(dst),      make_float4(o[0],  o[1],  o[2],  o[3]));
            __stcs((float4*)(dst + 4),  make_float4(o[4],  o[5],  o[6],  o[7]));
            __stcs((float4*)(dst + 8),  make_float4(o[8],  o[9],  o[10], o[11]));
            __stcs((float4*)(dst + 12), make_float4(o[12], o[13], o[14], o[15]));
        }
        __syncthreads();
        if (tid == 0 && kc + AV_NST < NTOK / 32) AV_ISSUE(kc + AV_NST);
    }

#pragma unroll
    for (int i = 0; i < 4; i++)
#pragma unroll
        for (int hb = 0; hb < 2; hb++) {
            int grow = row0 + wm * 64 + i * 16 + (lane >> 2) + hb * 8;
            float inv = 1.0f / __ldg(&g_rowsum[grow]);
            float* dst = m_out + (size_t)grow * CDIM + col0 + wn * 32 + (lane & 3) * 2;
#pragma unroll
            for (int j = 0; j < 4; j++) {
                float2 o;
                o.x = acc[i][j][hb * 2]     * inv;
                o.y = acc[i][j][hb * 2 + 1] * inv;
                __stcs((float2*)(dst + j * 8), o);
            }
        }
}

// ---------------------------------------------------------------------------
extern "C" void kernel_launch(void* const* d_in, const int* in_sizes, int n_in,
                              void* d_out, int out_size)
{
    (void)in_sizes; (void)n_in; (void)out_size;
    const float* u  = (const float*)d_in[0];
    const float* z  = (const float*)d_in[1];
    const float* Wk = (const float*)d_in[2];
    const float* bk = (const float*)d_in[3];
    const float* Wv = (const float*)d_in[4];
    const float* bv = (const float*)d_in[5];
    const float* Wq = (const float*)d_in[6];
    const float* bq = (const float*)d_in[7];

    float* m_out    = (float*)d_out;                  // (8192, 512)
    float* attn_out = m_out + (size_t)NTOK * CDIM;    // (8192, 8192)

    cudaFuncSetAttribute(proj_k,   cudaFuncAttributeMaxDynamicSharedMemorySize, SM_TOTAL);
    cudaFuncSetAttribute(scores_k, cudaFuncAttributeMaxDynamicSharedMemorySize, SM_TOTAL);
    cudaFuncSetAttribute(av_k,     cudaFuncAttributeMaxDynamicSharedMemorySize, SM_TOTAL);

    split_all_kernel<<<4864, 256>>>(u, z, Wk, Wv, Wq);

    dim3 pgrid(CDIM / 128, NTOK / 128, 3);            // (4, 64, 3)
    proj_k<<<pgrid, 256, SM_TOTAL>>>(bk, bv, bq);

    dim3 sgrid(NTOK / 128, NTOK / 128);               // (64, 64)
    scores_k<<<sgrid, 256, SM_TOTAL>>>();

    dim3 agrid(CDIM / 128, NTOK / 128);               // (4, 64)
    av_k<<<agrid, 256, SM_TOTAL>>>(m_out, attn_out);
}

// round 17
// speedup vs baseline: 1.0216x; 1.0216x over previous
#include <cuda_runtime.h>
#include <cuda_bf16.h>
#include <cuda_fp16.h>
#include <cstdint>

#define NTOK  8192
#define INDIM 1024
#define CDIM  512

using bf16 = __nv_bfloat16;

// bf16 hi/lo packed tile: 128 rows x 32 cols, pitch 80 B; hi then lo. 20480 B.
#define TILE_B  20480
#define TILE_HI 10240
// fp16 single-plane tile: 128 rows x 32 cols, pitch 80 B. 10240 B.
#define PTILE   10240

// ---------------------------------------------------------------------------
__device__ __align__(1024) char g_Sp[(size_t)2048 * TILE_B];    // S: [rb 64][kc 32] bf16 hi/lo
__device__ __align__(1024) char g_Wp[3][(size_t)128 * TILE_B];  // W: [rb 4][kc 32] bf16 hi/lo
__device__ __align__(1024) char g_Qp[(size_t)1024 * TILE_B];    // Q: [rb 64][kc 16] bf16 hi/lo
__device__ __align__(1024) char g_Kp[(size_t)1024 * TILE_B];    // K: [rb 64][kc 16] bf16 hi/lo
__device__ __align__(1024) char g_Vtp[(size_t)1024 * PTILE];    // V^T: [rb 4][kc 256] fp16
__device__ __align__(1024) char g_Pp[(size_t)16384 * PTILE];    // P: [rb 64][kc 256] fp16
__device__ float g_rowsum[NTOK];

// ---------------------------------------------------------------------------
__device__ __forceinline__ uint32_t su32(const void* p) {
    uint32_t a;
    asm("{ .reg .u64 t; cvta.to.shared.u64 t, %1; cvt.u32.u64 %0, t; }" : "=r"(a) : "l"(p));
    return a;
}
__device__ __forceinline__ void mbar_init(uint32_t m, uint32_t c) {
    asm volatile("mbarrier.init.shared.b64 [%0], %1;" :: "r"(m), "r"(c) : "memory");
}
__device__ __forceinline__ void mbar_expect(uint32_t m, uint32_t bytes) {
    asm volatile("mbarrier.arrive.expect_tx.shared.b64 _, [%0], %1;" :: "r"(m), "r"(bytes) : "memory");
}
__device__ __forceinline__ void mbar_wait(uint32_t m, uint32_t parity) {
    asm volatile(
        "{\n\t.reg .pred P1;\n\t"
        "WL_%=:\n\t"
        "mbarrier.try_wait.parity.acquire.cta.shared::cta.b64 P1, [%0], %1, 0x989680;\n\t"
        "@P1 bra.uni WD_%=;\n\t"
        "bra.uni WL_%=;\n\t"
        "WD_%=:\n\t}"
        :: "r"(m), "r"(parity) : "memory");
}
__device__ __forceinline__ void bulk_g2s(uint32_t sdst, const void* gsrc, uint32_t bytes, uint32_t mbar) {
    asm volatile(
        "cp.async.bulk.shared::cluster.global.mbarrier::complete_tx::bytes [%0], [%1], %2, [%3];"
        :: "r"(sdst), "l"(__cvta_generic_to_global(gsrc)), "r"(bytes), "r"(mbar) : "memory");
}
__device__ __forceinline__ void ldm4(uint32_t& r0, uint32_t& r1, uint32_t& r2, uint32_t& r3, uint32_t a) {
    asm volatile("ldmatrix.sync.aligned.m8n8.x4.shared.b16 {%0,%1,%2,%3}, [%4];"
                 : "=r"(r0), "=r"(r1), "=r"(r2), "=r"(r3) : "r"(a));
}
__device__ __forceinline__ void mma16816(float* c, const uint32_t* a, const uint32_t* b) {
    asm volatile(
        "mma.sync.aligned.m16n8k16.row.col.f32.bf16.bf16.f32 "
        "{%0,%1,%2,%3}, {%4,%5,%6,%7}, {%8,%9}, {%0,%1,%2,%3};"
        : "+f"(c[0]), "+f"(c[1]), "+f"(c[2]), "+f"(c[3])
        : "r"(a[0]), "r"(a[1]), "r"(a[2]), "r"(a[3]), "r"(b[0]), "r"(b[1]));
}
__device__ __forceinline__ void mmaf16(float* c, const uint32_t* a, const uint32_t* b) {
    asm volatile(
        "mma.sync.aligned.m16n8k16.row.col.f32.f16.f16.f32 "
        "{%0,%1,%2,%3}, {%4,%5,%6,%7}, {%8,%9}, {%0,%1,%2,%3};"
        : "+f"(c[0]), "+f"(c[1]), "+f"(c[2]), "+f"(c[3])
        : "r"(a[0]), "r"(a[1]), "r"(a[2]), "r"(a[3]), "r"(b[0]), "r"(b[1]));
}
__device__ __forceinline__ void split2(float v, bf16& h, bf16& l) {
    h = __float2bfloat16(v);
    l = __float2bfloat16(v - __bfloat162float(h));
}
__device__ __forceinline__ uint32_t packbf(bf16 a, bf16 b) {
    return ((uint32_t)__bfloat16_as_ushort(b) << 16) | __bfloat16_as_ushort(a);
}

// ---------------------------------------------------------------------------
// bf16 GEMM SMEM: stage = [A_HI][A_LO][B_HI][B_LO] = 40960 B; x2 stages.
#define A_HI   0
#define A_LO   10240
#define B_HI   20480
#define B_LO   30720
#define STAGE  40960
#define SM_RSUM 81920
#define SM_MBAR 82432
#define SM_TOTAL 82464
// av (fp16) SMEM: stage = [P0 10240][V0 10240][P1 10240][V1 10240] = 40960; x2.
#define AVSTAGE 40960

// bf16 x3-combo chunk into acc[4][4][4].
__device__ __forceinline__ void compute_stage(uint32_t sb, int wm, int wn, int lane,
                                              float acc[4][4][4])
{
    const uint32_t a_off = (lane & 15) * 80 + (lane >> 4) * 16;
    const uint32_t b_off = ((lane & 7) + ((lane >> 4) & 1) * 8) * 80 + ((lane >> 3) & 1) * 16;
#pragma unroll
    for (int kk = 0; kk < 2; kk++) {
        uint32_t bh[8], bl[8], a[16];
#pragma unroll
        for (int jj = 0; jj < 2; jj++) {
            uint32_t ad = sb + B_HI + (wn * 32 + jj * 16) * 80 + kk * 32 + b_off;
            ldm4(bh[jj * 4], bh[jj * 4 + 1], bh[jj * 4 + 2], bh[jj * 4 + 3], ad);
            ldm4(bl[jj * 4], bl[jj * 4 + 1], bl[jj * 4 + 2], bl[jj * 4 + 3], ad + (B_LO - B_HI));
        }
#pragma unroll
        for (int i = 0; i < 4; i++) {
            uint32_t ad = sb + A_HI + (wm * 64 + i * 16) * 80 + kk * 32 + a_off;
            ldm4(a[i * 4], a[i * 4 + 1], a[i * 4 + 2], a[i * 4 + 3], ad);
        }
#pragma unroll
        for (int i = 0; i < 4; i++)
#pragma unroll
            for (int j = 0; j < 4; j++) {
                mma16816(acc[i][j], &a[i * 4], &bh[j * 2]);
                mma16816(acc[i][j], &a[i * 4], &bl[j * 2]);
            }
#pragma unroll
        for (int i = 0; i < 4; i++) {
            uint32_t ad = sb + A_LO + (wm * 64 + i * 16) * 80 + kk * 32 + a_off;
            ldm4(a[i * 4], a[i * 4 + 1], a[i * 4 + 2], a[i * 4 + 3], ad);
        }
#pragma unroll
        for (int i = 0; i < 4; i++)
#pragma unroll
            for (int j = 0; j < 4; j++)
                mma16816(acc[i][j], &a[i * 4], &bh[j * 2]);
    }
}

// fp16 1-combo sub-tile (av): A at sb, B at sb+PTILE.
__device__ __forceinline__ void compute_av(uint32_t sb, int wm, int wn, int lane,
                                           float acc[4][4][4])
{
    const uint32_t a_off = (lane & 15) * 80 + (lane >> 4) * 16;
    const uint32_t b_off = ((lane & 7) + ((lane >> 4) & 1) * 8) * 80 + ((lane >> 3) & 1) * 16;
#pragma unroll
    for (int kk = 0; kk < 2; kk++) {
        uint32_t bh[8], a[16];
#pragma unroll
        for (int jj = 0; jj < 2; jj++) {
            uint32_t ad = sb + PTILE + (wn * 32 + jj * 16) * 80 + kk * 32 + b_off;
            ldm4(bh[jj * 4], bh[jj * 4 + 1], bh[jj * 4 + 2], bh[jj * 4 + 3], ad);
        }
#pragma unroll
        for (int i = 0; i < 4; i++) {
            uint32_t ad = sb + (wm * 64 + i * 16) * 80 + kk * 32 + a_off;
            ldm4(a[i * 4], a[i * 4 + 1], a[i * 4 + 2], a[i * 4 + 3], ad);
        }
#pragma unroll
        for (int i = 0; i < 4; i++)
#pragma unroll
            for (int j = 0; j < 4; j++)
                mmaf16(acc[i][j], &a[i * 4], &bh[j * 2]);
    }
}

#define ISSUE_CHUNK(kc)                                                                      \
    do {                                                                                     \
        uint32_t s_ = sb + ((kc) & 1) * STAGE;                                               \
        uint32_t m_ = ((kc) & 1) ? mb1 : mb0;                                                \
        mbar_expect(m_, 2 * TILE_B);                                                         \
        bulk_g2s(s_,        Abase + (size_t)(at0 + (kc)) * TILE_B, TILE_B, m_);              \
        bulk_g2s(s_ + B_HI, Bbase + (size_t)(bt0 + (kc)) * TILE_B, TILE_B, m_);              \
    } while (0)

#define PACKED_MAINLOOP(AbaseE, at0E, BbaseE, bt0E, NCH)                                     \
    const char* Abase = (AbaseE); const char* Bbase = (BbaseE);                              \
    const int at0 = (at0E), bt0 = (bt0E);                                                    \
    if (tid == 0) { mbar_init(mb0, 1); mbar_init(mb1, 1); }                                  \
    __syncthreads();                                                                         \
    if (tid == 0) { ISSUE_CHUNK(0); ISSUE_CHUNK(1); }                                        \
    for (int kc = 0; kc < (NCH); kc++) {                                                     \
        mbar_wait((kc & 1) ? mb1 : mb0, (uint32_t)((kc >> 1) & 1));                          \
        compute_stage(sb + (kc & 1) * STAGE, wm, wn, lane, acc);                             \
        __syncthreads();                                                                     \
        if (tid == 0 && kc + 2 < (NCH)) ISSUE_CHUNK(kc + 2);                                 \
    }

// av chunk = 2 tiles: P(2kc), V(2kc), P(2kc+1), V(2kc+1) into one 40 KB stage.
#define AV_ISSUE(kc)                                                                         \
    do {                                                                                     \
        uint32_t s_ = sb + ((kc) & 1) * AVSTAGE;                                             \
        uint32_t m_ = ((kc) & 1) ? mb1 : mb0;                                                \
        mbar_expect(m_, 4 * PTILE);                                                          \
        bulk_g2s(s_,             g_Pp  + (size_t)(at0 + 2 * (kc))     * PTILE, PTILE, m_);   \
        bulk_g2s(s_ + PTILE,     g_Vtp + (size_t)(bt0 + 2 * (kc))     * PTILE, PTILE, m_);   \
        bulk_g2s(s_ + 2 * PTILE, g_Pp  + (size_t)(at0 + 2 * (kc) + 1) * PTILE, PTILE, m_);   \
        bulk_g2s(s_ + 3 * PTILE, g_Vtp + (size_t)(bt0 + 2 * (kc) + 1) * PTILE, PTILE, m_);   \
    } while (0)

#define GEMM_PROLOG                                                   \
    extern __shared__ char smem[];                                    \
    const uint32_t sb = su32(smem);                                   \
    const uint32_t mb0 = sb + SM_MBAR, mb1 = sb + SM_MBAR + 8;        \
    const int tid = threadIdx.x;                                      \
    const int lane = tid & 31, warp = tid >> 5;                       \
    const int wm = warp >> 2, wn = warp & 3;                          \
    float acc[4][4][4];                                               \
    _Pragma("unroll") for (int i = 0; i < 4; i++)                     \
    _Pragma("unroll") for (int j = 0; j < 4; j++)                     \
    _Pragma("unroll") for (int k = 0; k < 4; k++) acc[i][j][k] = 0.0f;

// ---------------------------------------------------------------------------
// Fused split: blocks [0, 4096) -> S (also zeroes rowsum); [4096, 4864) -> W.
__global__ __launch_bounds__(256) void split_all_kernel(
    const float* __restrict__ u, const float* __restrict__ z,
    const float* __restrict__ Wk, const float* __restrict__ Wv, const float* __restrict__ Wq)
{
    if (blockIdx.x < 4096) {
        int idx = blockIdx.x * 256 + threadIdx.x;
        if (idx < NTOK) g_rowsum[idx] = 0.0f;
        int row = idx >> 7;
        int c0 = (idx & 127) * 8;
        const float* src = (c0 < 512) ? (u + (size_t)row * 512 + c0)
                                      : (z + (size_t)row * 512 + c0 - 512);
        float4 a = *(const float4*)src;
        float4 b = *(const float4*)(src + 4);
        float x[8] = {a.x, a.y, a.z, a.w, b.x, b.y, b.z, b.w};
        uint32_t hw[4], lw[4];
#pragma unroll
        for (int i = 0; i < 4; i++) {
            bf16 h0, l0, h1, l1;
            split2(x[2 * i], h0, l0); split2(x[2 * i + 1], h1, l1);
            hw[i] = packbf(h0, h1); lw[i] = packbf(l0, l1);
        }
        size_t t = (size_t)(row >> 7) * 32 + (c0 >> 5);
        size_t off = t * TILE_B + (size_t)(row & 127) * 80 + (c0 & 31) * 2;
        *(uint4*)(g_Sp + off)           = make_uint4(hw[0], hw[1], hw[2], hw[3]);
        *(uint4*)(g_Sp + off + TILE_HI) = make_uint4(lw[0], lw[1], lw[2], lw[3]);
    } else {
        int wb = blockIdx.x - 4096;            // 0..767
        int sel = wb >> 8;                     // 256 blocks per W
        const float* W = (sel == 0) ? Wk : (sel == 1) ? Wv : Wq;
        int idx = (wb & 255) * 256 + threadIdx.x;
        int row = idx >> 7;
        int c0 = (idx & 127) * 8;
        const float* src = W + (size_t)row * INDIM + c0;
        float4 a = *(const float4*)src;
        float4 b = *(const float4*)(src + 4);
        float x[8] = {a.x, a.y, a.z, a.w, b.x, b.y, b.z, b.w};
        uint32_t hw[4], lw[4];
#pragma unroll
        for (int i = 0; i < 4; i++) {
            bf16 h0, l0, h1, l1;
            split2(x[2 * i], h0, l0); split2(x[2 * i + 1], h1, l1);
            hw[i] = packbf(h0, h1); lw[i] = packbf(l0, l1);
        }
        size_t t = (size_t)(row >> 7) * 32 + (c0 >> 5);
        size_t off = t * TILE_B + (size_t)(row & 127) * 80 + (c0 & 31) * 2;
        *(uint4*)(g_Wp[sel] + off)           = make_uint4(hw[0], hw[1], hw[2], hw[3]);
        *(uint4*)(g_Wp[sel] + off + TILE_HI) = make_uint4(lw[0], lw[1], lw[2], lw[3]);
    }
}

// ---------------------------------------------------------------------------
// Projection (all three in one launch): tile 128x128, K=1024.
// blockIdx.z: 0->K (bf16 hi/lo), 1->V (transposed fp16), 2->Q (bf16 hi/lo)
__global__ __launch_bounds__(256, 2) void proj_k(
    const float* __restrict__ bk, const float* __restrict__ bv, const float* __restrict__ bq)
{
    GEMM_PROLOG;
    const int sel = blockIdx.z;
    const float* bias = (sel == 0) ? bk : (sel == 1) ? bv : bq;
    const int row0 = blockIdx.y * 128, col0 = blockIdx.x * 128;
    {
        PACKED_MAINLOOP(g_Sp, (row0 >> 7) * 32, g_Wp[sel], (col0 >> 7) * 32, INDIM / 32);
    }

    if (sel != 1) {
        char* outp = (sel == 2) ? g_Qp : g_Kp;
#pragma unroll
        for (int i = 0; i < 4; i++)
#pragma unroll
            for (int hb = 0; hb < 2; hb++) {
                int grow = row0 + wm * 64 + i * 16 + (lane >> 2) + hb * 8;
                char* base = outp
                    + ((size_t)(grow >> 7) * 16 + (col0 >> 5) + wn) * TILE_B
                    + (size_t)(grow & 127) * 80 + (lane & 3) * 4;
#pragma unroll
                for (int j = 0; j < 4; j++) {
                    int gcol = col0 + wn * 32 + j * 8 + (lane & 3) * 2;
                    float v0 = acc[i][j][hb * 2]     + __ldg(bias + gcol);
                    float v1 = acc[i][j][hb * 2 + 1] + __ldg(bias + gcol + 1);
                    bf16 h0, l0, h1, l1;
                    split2(v0, h0, l0); split2(v1, h1, l1);
                    *(uint32_t*)(base + j * 16)           = packbf(h0, h1);
                    *(uint32_t*)(base + j * 16 + TILE_HI) = packbf(l0, l1);
                }
            }
    } else {
        // V: fp16, transpose via smem (single plane, pitch 272 B; [c 128][tok 128]).
#pragma unroll
        for (int i = 0; i < 4; i++)
#pragma unroll
            for (int hb = 0; hb < 2; hb++) {
                int tok = wm * 64 + i * 16 + (lane >> 2) + hb * 8;
#pragma unroll
                for (int j = 0; j < 4; j++) {
                    int cl = wn * 32 + j * 8 + (lane & 3) * 2;
                    float v0 = acc[i][j][hb * 2]     + __ldg(bias + col0 + cl);
                    float v1 = acc[i][j][hb * 2 + 1] + __ldg(bias + col0 + cl + 1);
                    *(__half*)(smem + cl * 272 + tok * 2)       = __float2half(v0);
                    *(__half*)(smem + (cl + 1) * 272 + tok * 2) = __float2half(v1);
                }
            }
        __syncthreads();
        for (int q = tid; q < 2048; q += 256) {
            int c = q >> 4, t8 = (q & 15) * 8;
            uint4 vh = *(uint4*)(smem + c * 272 + t8 * 2);
            size_t t = (size_t)(col0 >> 7) * 256 + ((row0 + t8) >> 5);
            size_t off = t * PTILE + (size_t)c * 80 + (t8 & 31) * 2;
            *(uint4*)(g_Vtp + off) = vh;
        }
    }
}

// ---------------------------------------------------------------------------
// Scores: P = exp(QK^T/sqrt(512)) unnormalized, diag=0, stored fp16; rowsum.
// Off-diagonal CTAs (row0 != col0) take a compare-free epilogue.
__global__ __launch_bounds__(256, 2) void scores_k()
{
    GEMM_PROLOG;
    const int row0 = blockIdx.y * 128, col0 = blockIdx.x * 128;
    float* s_rsum = (float*)(smem + SM_RSUM);
    if (tid < 128) s_rsum[tid] = 0.0f;
    {
        PACKED_MAINLOOP(g_Qp, (row0 >> 7) * 16, g_Kp, (col0 >> 7) * 16, CDIM / 32);
    }

    // exp(x/sqrt(512)) = exp2(x * log2(e)/sqrt(512))
    const float scale2 = 0.06375871712f;
    const bool offdiag = (row0 != col0);
#pragma unroll
    for (int i = 0; i < 4; i++)
#pragma unroll
        for (int hb = 0; hb < 2; hb++) {
            int rloc = wm * 64 + i * 16 + (lane >> 2) + hb * 8;
            int grow = row0 + rloc;
            char* base = g_Pp
                + ((size_t)(grow >> 7) * 256 + (col0 >> 5) + wn) * PTILE
                + (size_t)(grow & 127) * 80 + (lane & 3) * 4;
            float part = 0.0f;
            if (offdiag) {
#pragma unroll
                for (int j = 0; j < 4; j++) {
                    float p0 = exp2f(acc[i][j][hb * 2]     * scale2);
                    float p1 = exp2f(acc[i][j][hb * 2 + 1] * scale2);
                    part += p0 + p1;
                    __half2 ph = __floats2half2_rn(p0, p1);
                    __stcs((unsigned int*)(base + j * 16), *(unsigned int*)&ph);
                }
            } else {
#pragma unroll
                for (int j = 0; j < 4; j++) {
                    int gcol = col0 + wn * 32 + j * 8 + (lane & 3) * 2;
                    float p0 = (grow == gcol)     ? 0.0f : exp2f(acc[i][j][hb * 2]     * scale2);
                    float p1 = (grow == gcol + 1) ? 0.0f : exp2f(acc[i][j][hb * 2 + 1] * scale2);
                    part += p0 + p1;
                    __half2 ph = __floats2half2_rn(p0, p1);
                    __stcs((unsigned int*)(base + j * 16), *(unsigned int*)&ph);
                }
            }
            part += __shfl_xor_sync(0xFFFFFFFF, part, 1);
            part += __shfl_xor_sync(0xFFFFFFFF, part, 2);
            if ((lane & 3) == 0) atomicAdd(&s_rsum[rloc], part);
        }
    __syncthreads();
    if (tid < 128) atomicAdd(&g_rowsum[row0 + tid], s_rsum[tid]);
}

// ---------------------------------------------------------------------------
// AV: m_bar = (P @ V) / rowsum, fp16, tile 128x128, K=8192.
// K-chunk 64 (2 tiles per stage): halves per-chunk fixed overhead.
// FUSED: each CTA converts its quarter of the P row-block (kc>>5 == blockIdx.x)
// from smem to normalized fp32 attn (both sub-tiles).
__global__ __launch_bounds__(256, 2) void av_k(float* __restrict__ m_out,
                                               float* __restrict__ attn)
{
    GEMM_PROLOG;
    const int row0 = blockIdx.y * 128, col0 = blockIdx.x * 128;
    const int cvt_sel = blockIdx.x;
    const int crow = tid >> 1;               // conversion row 0..127
    const int cseg = (tid & 1) * 16;         // col segment 0 or 16
    const float cinv = 1.0f / g_rowsum[row0 + crow];

    const int at0 = (row0 >> 7) * 256, bt0 = (col0 >> 7) * 256;
    if (tid == 0) { mbar_init(mb0, 1); mbar_init(mb1, 1); }
    __syncthreads();
    if (tid == 0) { AV_ISSUE(0); AV_ISSUE(1); }
    for (int kc = 0; kc < 128; kc++) {
        uint32_t st = sb + (kc & 1) * AVSTAGE;
        mbar_wait((kc & 1) ? mb1 : mb0, (uint32_t)((kc >> 1) & 1));
        compute_av(st,             wm, wn, lane, acc);
        compute_av(st + 2 * PTILE, wm, wn, lane, acc);
        if ((kc >> 5) == cvt_sel) {
#pragma unroll
            for (int h = 0; h < 2; h++) {
                uint32_t soff = (st - sb) + h * 2 * PTILE + (uint32_t)crow * 80 + cseg * 2;
                uint4 h0 = *(uint4*)(smem + soff);
                uint4 h1 = *(uint4*)(smem + soff + 16);
                uint32_t hw[8] = {h0.x, h0.y, h0.z, h0.w, h1.x, h1.y, h1.z, h1.w};
                float o[16];
#pragma unroll
                for (int k = 0; k < 8; k++) {
                    float2 f = __half22float2(*reinterpret_cast<__half2*>(&hw[k]));
                    o[2 * k]     = f.x * cinv;
                    o[2 * k + 1] = f.y * cinv;
                }
                float* dst = attn + (size_t)(row0 + crow) * NTOK + (2 * kc + h) * 32 + cseg;
                __stcs((float4*)(dst),      make_float4(o[0],  o[1],  o[2],  o[3]));
                __stcs((float4*)(dst + 4),  make_float4(o[4],  o[5],  o[6],  o[7]));
                __stcs((float4*)(dst + 8),  make_float4(o[8],  o[9],  o[10], o[11]));
                __stcs((float4*)(dst + 12), make_float4(o[12], o[13], o[14], o[15]));
            }
        }
        __syncthreads();
        if (tid == 0 && kc + 2 < 128) AV_ISSUE(kc + 2);
    }

#pragma unroll
    for (int i = 0; i < 4; i++)
#pragma unroll
        for (int hb = 0; hb < 2; hb++) {
            int grow = row0 + wm * 64 + i * 16 + (lane >> 2) + hb * 8;
            float inv = 1.0f / __ldg(&g_rowsum[grow]);
            float* dst = m_out + (size_t)grow * CDIM + col0 + wn * 32 + (lane & 3) * 2;
#pragma unroll
            for (int j = 0; j < 4; j++) {
                float2 o;
                o.x = acc[i][j][hb * 2]     * inv;
                o.y = acc[i][j][hb * 2 + 1] * inv;
                __stcs((float2*)(dst + j * 8), o);
            }
        }
}

// ---------------------------------------------------------------------------
extern "C" void kernel_launch(void* const* d_in, const int* in_sizes, int n_in,
                              void* d_out, int out_size)
{
    (void)in_sizes; (void)n_in; (void)out_size;
    const float* u  = (const float*)d_in[0];
    const float* z  = (const float*)d_in[1];
    const float* Wk = (const float*)d_in[2];
    const float* bk = (const float*)d_in[3];
    const float* Wv = (const float*)d_in[4];
    const float* bv = (const float*)d_in[5];
    const float* Wq = (const float*)d_in[6];
    const float* bq = (const float*)d_in[7];

    float* m_out    = (float*)d_out;                  // (8192, 512)
    float* attn_out = m_out + (size_t)NTOK * CDIM;    // (8192, 8192)

    cudaFuncSetAttribute(proj_k,   cudaFuncAttributeMaxDynamicSharedMemorySize, SM_TOTAL);
    cudaFuncSetAttribute(scores_k, cudaFuncAttributeMaxDynamicSharedMemorySize, SM_TOTAL);
    cudaFuncSetAttribute(av_k,     cudaFuncAttributeMaxDynamicSharedMemorySize, SM_TOTAL);

    split_all_kernel<<<4864, 256>>>(u, z, Wk, Wv, Wq);

    dim3 pgrid(CDIM / 128, NTOK / 128, 3);            // (4, 64, 3)
    proj_k<<<pgrid, 256, SM_TOTAL>>>(bk, bv, bq);

    dim3 sgrid(NTOK / 128, NTOK / 128);               // (64, 64)
    scores_k<<<sgrid, 256, SM_TOTAL>>>();

    dim3 agrid(CDIM / 128, NTOK / 128);               // (4, 64)
    av_k<<<agrid, 256, SM_TOTAL>>>(m_out, attn_out);
}